// round 11
// baseline (speedup 1.0000x reference)
#include <cuda_runtime.h>
#include <cstdint>
#include <cstddef>

typedef unsigned long long u64;
typedef unsigned int u32;

#define B_SZ 64
#define T_SZ 2048
#define H_SZ 256
#define G4   1024   // 4*H

// scratch: natural layout [m][gate*256+u] (gemm output)
__device__ float g_xg[(size_t)B_SZ * T_SZ * G4];
// scratch: gate-interleaved layout [m][u*4+gate] (scan input)
__device__ float g_xgi[(size_t)B_SZ * T_SZ * G4];

// ---------------- f32x2 helpers ----------------
__device__ __forceinline__ u64 pk2(float lo, float hi) {
    u64 r; asm("mov.b64 %0, {%1, %2};" : "=l"(r) : "f"(lo), "f"(hi)); return r;
}
__device__ __forceinline__ u64 dup2(float a) {
    u64 r; asm("mov.b64 %0, {%1, %1};" : "=l"(r) : "f"(a)); return r;
}
__device__ __forceinline__ u64 fma2(u64 a, u64 b, u64 c) {
    u64 d; asm("fma.rn.f32x2 %0, %1, %2, %3;" : "=l"(d) : "l"(a), "l"(b), "l"(c)); return d;
}
__device__ __forceinline__ u64 add2(u64 a, u64 b) {
    u64 d; asm("add.rn.f32x2 %0, %1, %2;" : "=l"(d) : "l"(a), "l"(b)); return d;
}
__device__ __forceinline__ void unpk(u64 v, float& lo, float& hi) {
    asm("mov.b64 {%0, %1}, %2;" : "=f"(lo), "=f"(hi) : "l"(v));
}

// ---------------- cluster / mbarrier / bulk helpers ----------------
__device__ __forceinline__ u32 smem_u32(const void* p) {
    u32 a;
    asm("{ .reg .u64 t; cvta.to.shared.u64 t, %1; cvt.u32.u64 %0, t; }" : "=r"(a) : "l"(p));
    return a;
}
__device__ __forceinline__ u32 mapa_sh(u32 a, u32 rk) {
    u32 r; asm("mapa.shared::cluster.u32 %0, %1, %2;" : "=r"(r) : "r"(a), "r"(rk)); return r;
}
__device__ __forceinline__ void cluster_sync_() {
    asm volatile("barrier.cluster.arrive.aligned;" ::: "memory");
    asm volatile("barrier.cluster.wait.aligned;" ::: "memory");
}
__device__ __forceinline__ void mbar_init(u32 a, u32 cnt) {
    asm volatile("mbarrier.init.shared.b64 [%0], %1;" :: "r"(a), "r"(cnt) : "memory");
}
__device__ __forceinline__ void mbar_expect(u32 a, u32 bytes) {
    asm volatile("mbarrier.arrive.expect_tx.shared.b64 _, [%0], %1;" :: "r"(a), "r"(bytes) : "memory");
}
__device__ __forceinline__ void mbar_wait(u32 a, u32 ph) {
    asm volatile(
        "{\n\t.reg .pred P;\n\t"
        "MW%=:\n\t"
        "mbarrier.try_wait.parity.acquire.cta.shared::cta.b64 P, [%0], %1, 0x989680;\n\t"
        "@!P bra MW%=;\n\t}"
        :: "r"(a), "r"(ph) : "memory");
}
// bulk smem(cta) -> smem(cluster) copy, tx-completion at dest CTA's mbarrier
__device__ __forceinline__ void bulk_s2s(u32 dst, u32 src, u32 bytes, u32 mb) {
    asm volatile(
        "cp.async.bulk.shared::cluster.shared::cta.mbarrier::complete_tx::bytes [%0], [%1], %2, [%3];"
        :: "r"(dst), "r"(src), "r"(bytes), "r"(mb) : "memory");
}

// ---------------- activations (exact, MUFU-based) ----------------
__device__ __forceinline__ float sigm(float x) {
    return __fdividef(1.0f, 1.0f + __expf(-x));
}
__device__ __forceinline__ float tanh_(float x) {
    return 1.0f - __fdividef(2.0f, __expf(2.0f * x) + 1.0f);
}

// =====================================================================
// Phase 1: g_xg[m][1024] = x[m][256] @ W_i[256][1024] + bias
// (unchanged, proven 1.35ms)
// =====================================================================
__global__ __launch_bounds__(256, 2) void xw_gemm(
    const float* __restrict__ A,
    const float* __restrict__ W,
    const float* __restrict__ bias)
{
    __shared__ float As[2][16][132];
    __shared__ float Bs[2][16][132];

    const int tid = threadIdx.x;
    const int tx = tid & 15;
    const int ty = tid >> 4;
    const int mBase = blockIdx.y * 128;
    const int nBase = blockIdx.x * 128;

    const int arow0 = tid >> 2,         akq0 = tid & 3;
    const int arow1 = (tid + 256) >> 2, akq1 = (tid + 256) & 3;
    const int bk0   = tid >> 5,         bnq0 = tid & 31;
    const int bk1   = (tid + 256) >> 5, bnq1 = (tid + 256) & 31;

    u64 acc[8][4];
    {
        const float* bp = bias + nBase + tx * 8;
        u64 b0 = pk2(bp[0], bp[1]);
        u64 b1 = pk2(bp[2], bp[3]);
        u64 b2 = pk2(bp[4], bp[5]);
        u64 b3 = pk2(bp[6], bp[7]);
#pragma unroll
        for (int i = 0; i < 8; i++) { acc[i][0] = b0; acc[i][1] = b1; acc[i][2] = b2; acc[i][3] = b3; }
    }

    float4 a_r0, a_r1, b_r0, b_r1;
    a_r0 = *(const float4*)(A + (size_t)(mBase + arow0) * 256 + akq0 * 4);
    a_r1 = *(const float4*)(A + (size_t)(mBase + arow1) * 256 + akq1 * 4);
    b_r0 = *(const float4*)(W + (size_t)bk0 * 1024 + nBase + bnq0 * 4);
    b_r1 = *(const float4*)(W + (size_t)bk1 * 1024 + nBase + bnq1 * 4);
    As[0][akq0 * 4 + 0][arow0] = a_r0.x; As[0][akq0 * 4 + 1][arow0] = a_r0.y;
    As[0][akq0 * 4 + 2][arow0] = a_r0.z; As[0][akq0 * 4 + 3][arow0] = a_r0.w;
    As[0][akq1 * 4 + 0][arow1] = a_r1.x; As[0][akq1 * 4 + 1][arow1] = a_r1.y;
    As[0][akq1 * 4 + 2][arow1] = a_r1.z; As[0][akq1 * 4 + 3][arow1] = a_r1.w;
    *(float4*)&Bs[0][bk0][bnq0 * 4] = b_r0;
    *(float4*)&Bs[0][bk1][bnq1 * 4] = b_r1;
    __syncthreads();

    int p = 0;
#pragma unroll 1
    for (int kc = 0; kc < 16; kc++) {
        if (kc < 15) {
            const int kb = (kc + 1) * 16;
            a_r0 = *(const float4*)(A + (size_t)(mBase + arow0) * 256 + kb + akq0 * 4);
            a_r1 = *(const float4*)(A + (size_t)(mBase + arow1) * 256 + kb + akq1 * 4);
            b_r0 = *(const float4*)(W + (size_t)(kb + bk0) * 1024 + nBase + bnq0 * 4);
            b_r1 = *(const float4*)(W + (size_t)(kb + bk1) * 1024 + nBase + bnq1 * 4);
        }
#pragma unroll
        for (int k = 0; k < 16; k++) {
            float4 a0 = *(float4*)&As[p][k][ty * 8];
            float4 a1 = *(float4*)&As[p][k][ty * 8 + 4];
            float4 b0 = *(float4*)&Bs[p][k][tx * 8];
            float4 b1 = *(float4*)&Bs[p][k][tx * 8 + 4];
            u64 bb0 = pk2(b0.x, b0.y), bb1 = pk2(b0.z, b0.w);
            u64 bb2 = pk2(b1.x, b1.y), bb3 = pk2(b1.z, b1.w);
            float aa[8] = {a0.x, a0.y, a0.z, a0.w, a1.x, a1.y, a1.z, a1.w};
#pragma unroll
            for (int i = 0; i < 8; i++) {
                u64 ad = dup2(aa[i]);
                acc[i][0] = fma2(ad, bb0, acc[i][0]);
                acc[i][1] = fma2(ad, bb1, acc[i][1]);
                acc[i][2] = fma2(ad, bb2, acc[i][2]);
                acc[i][3] = fma2(ad, bb3, acc[i][3]);
            }
        }
        if (kc < 15) {
            const int pn = p ^ 1;
            As[pn][akq0 * 4 + 0][arow0] = a_r0.x; As[pn][akq0 * 4 + 1][arow0] = a_r0.y;
            As[pn][akq0 * 4 + 2][arow0] = a_r0.z; As[pn][akq0 * 4 + 3][arow0] = a_r0.w;
            As[pn][akq1 * 4 + 0][arow1] = a_r1.x; As[pn][akq1 * 4 + 1][arow1] = a_r1.y;
            As[pn][akq1 * 4 + 2][arow1] = a_r1.z; As[pn][akq1 * 4 + 3][arow1] = a_r1.w;
            *(float4*)&Bs[pn][bk0][bnq0 * 4] = b_r0;
            *(float4*)&Bs[pn][bk1][bnq1 * 4] = b_r1;
            __syncthreads();
            p = pn;
        }
    }

#pragma unroll
    for (int i = 0; i < 8; i++) {
        float o[8];
        unpk(acc[i][0], o[0], o[1]); unpk(acc[i][1], o[2], o[3]);
        unpk(acc[i][2], o[4], o[5]); unpk(acc[i][3], o[6], o[7]);
        float* cp = g_xg + (size_t)(mBase + ty * 8 + i) * 1024 + nBase + tx * 8;
        *(float4*)(cp)     = make_float4(o[0], o[1], o[2], o[3]);
        *(float4*)(cp + 4) = make_float4(o[4], o[5], o[6], o[7]);
    }
}

// =====================================================================
// Repack: [m][gate*256+u] -> [m][u*4+gate]. (unchanged)
// =====================================================================
__global__ __launch_bounds__(256, 8) void repack()
{
    const size_t m = blockIdx.x;
    const int u = threadIdx.x;
    const float* src = g_xg + m * 1024;
    float4 v;
    v.x = src[u];
    v.y = src[256 + u];
    v.z = src[512 + u];
    v.w = src[768 + u];
    *(float4*)(g_xgi + m * 1024 + (size_t)u * 4) = v;
}

// =====================================================================
// Phase 2: recurrent scan with bulk-copy broadcast.
// Grid (8,16), cluster (8,1,1). hbuf[parity][chunk=src][row][slot16][2]:
// source src's 32 units as 16 u64 pairs; pair m4-group stored at slot
// (m4+src)&7 (rotation => conflict-free consumer LDS.128). Lane (w,j4,ks):
// unit u = rank*32+w*4+j4, k-slice = chunk ks. Per step:
//  - float4 xg prefetch -> mbar wait (parity, expect 4096B = 8 x 512B)
//  - GEMM: 8 chunks x 4 rows, ulonglong2 LDS + FFMA2
//  - warp shuffle reduce-scatter over ks -> owners (ks<4 = row) act
//  - storers STS h-pairs into 4-deep stage ring -> __syncthreads ->
//    tid0: wait_group.read 2, fence.proxy.async, 8 x cp.async.bulk
//    (512B each, incl self) -> commit_group.
// =====================================================================
__global__ __launch_bounds__(256, 1) __cluster_dims__(8, 1, 1)
void lstm_scan(const float* __restrict__ Wh, float* __restrict__ out)
{
    __shared__ u64 hbuf[2][8][4][8][2];   // 8KB: [parity][chunk][row][slot16][pair]
    __shared__ u64 stage[4][4][8][2];     // 2KB: [phase][row][slot16][pair]
    __shared__ u64 mbar[2];

    const int tid  = threadIdx.x;
    const int w    = tid >> 5;
    const int lane = tid & 31;
    const int j4   = lane >> 3;          // unit-within-group
    const int ks   = lane & 7;           // k-slice (= source chunk) / row id
    const int rank = blockIdx.x;
    const int grp  = blockIdx.y;
    const int u    = rank * 32 + w * 4 + j4;

    // --- weights packed along k: wp[g][m], k-pair kp = ks*16+m ---
    u64 wp[4][16];
#pragma unroll
    for (int m = 0; m < 16; m++) {
        const int kA = ks * 32 + 2 * m;
#pragma unroll
        for (int g = 0; g < 4; g++) {
            wp[g][m] = pk2(Wh[(size_t)kA * 1024 + g * 256 + u],
                           Wh[(size_t)(kA + 1) * 1024 + g * 256 + u]);
        }
    }

    // init: zero parity-0 hbuf (512 u64), init + arm both mbarriers
    {
        u64* hz = &hbuf[0][0][0][0][0];
        hz[tid] = 0ull; hz[tid + 256] = 0ull;
    }
    const u32 hb_l = smem_u32(&hbuf[0][0][0][0][0]);
    const u32 st_l = smem_u32(&stage[0][0][0][0]);
    const u32 mb_l = smem_u32(&mbar[0]);
    if (tid == 0) {
        mbar_init(mb_l, 1);
        mbar_init(mb_l + 8, 1);
        mbar_expect(mb_l, 4096);       // buffer 0: fed at t=1, used t=2
        mbar_expect(mb_l + 8, 4096);   // buffer 1: fed at t=0, used t=1
    }
    __syncthreads();
    cluster_sync_();   // peers armed + hbuf[0] zeroed everywhere

    // owner-lane constants (ks<4 => row ks)
    const int rowg = grp * 4 + ks;
    const size_t xgBase  = ((size_t)rowg * T_SZ) * 1024 + (size_t)u * 4;
    const size_t outBase = ((size_t)rowg * T_SZ) * H_SZ + u;

    // storers: ks<4 (row), even j4 (pair head). slot rotation by rank.
    const bool storer = (ks < 4) && ((j4 & 1) == 0);
    const int slot = (w + rank) & 7;

    // per-destination copy targets: dst chunk index = MY rank at every peer
    u32 dstc[8], mrem[8];
#pragma unroll
    for (int rk = 0; rk < 8; rk++) {
        dstc[rk] = mapa_sh(hb_l, (u32)rk) + (u32)rank * 512u;
        mrem[rk] = mapa_sh(mb_l, (u32)rk);
    }

    float c = 0.0f, h = 0.0f;
    u32 ph0 = 0, ph1 = 0;

#pragma unroll 1
    for (int t = 0; t < T_SZ; t++) {
        const int b = t & 1;

        // xg prefetch — single float4, issued before the wait
        float4 xq = make_float4(0.f, 0.f, 0.f, 0.f);
        if (ks < 4)
            xq = *(const float4*)(g_xgi + xgBase + (size_t)t * 1024);

        if (t > 0) {
            const u32 phb = b ? ph1 : ph0;
            mbar_wait(mb_l + (b << 3), phb);
            if (b) ph1 ^= 1; else ph0 ^= 1;
            if (tid == 0) mbar_expect(mb_l + (b << 3), 4096);  // re-arm for t+2
        }

        // ---- partial GEMM over this thread's chunk (k-slice ks) ----
        u64 acc[4][4];
#pragma unroll
        for (int r = 0; r < 4; r++)
#pragma unroll
            for (int g = 0; g < 4; g++) acc[r][g] = 0ull;

        const u64* cb = &hbuf[b][ks][0][0][0];   // my chunk base
#pragma unroll
        for (int i = 0; i < 8; i++) {
            const int sl = (i + ks) & 7;         // rotation swizzle
#pragma unroll
            for (int r = 0; r < 4; r++) {
                ulonglong2 hv = *(const ulonglong2*)(cb + r * 16 + sl * 2);
#pragma unroll
                for (int g = 0; g < 4; g++) {
                    acc[r][g] = fma2(hv.x, wp[g][2 * i],     acc[r][g]);
                    acc[r][g] = fma2(hv.y, wp[g][2 * i + 1], acc[r][g]);
                }
            }
        }

        // ---- warp reduce-scatter over ks (lane ends with row ks&3) ----
        const bool pb = (ks & 1);
        const bool qb = (ks & 2);
        u64 kk[4];
#pragma unroll
        for (int g = 0; g < 4; g++) {
            u64 sA = pb ? acc[0][g] : acc[1][g];
            u64 sB = pb ? acc[2][g] : acc[3][g];
            u64 rA = __shfl_xor_sync(0xffffffffu, sA, 1);
            u64 rB = __shfl_xor_sync(0xffffffffu, sB, 1);
            u64 k0 = add2(pb ? acc[1][g] : acc[0][g], rA);
            u64 k1 = add2(pb ? acc[3][g] : acc[2][g], rB);
            u64 s2 = qb ? k0 : k1;
            u64 r2 = __shfl_xor_sync(0xffffffffu, s2, 2);
            u64 kx = add2(qb ? k1 : k0, r2);
            kk[g] = add2(kx, __shfl_xor_sync(0xffffffffu, kx, 4));
        }

        // ---- owners: activations + output ----
        if (ks < 4) {
            float e0, e1;
            unpk(kk[0], e0, e1); const float gi = e0 + e1 + xq.x;
            unpk(kk[1], e0, e1); const float gf = e0 + e1 + xq.y;
            unpk(kk[2], e0, e1); const float gg = e0 + e1 + xq.z;
            unpk(kk[3], e0, e1); const float go = e0 + e1 + xq.w;

            c = sigm(gf) * c + sigm(gi) * tanh_(gg);
            h = sigm(go) * tanh_(c);

            out[outBase + (size_t)t * H_SZ] = h;
        }

        // ---- staged bulk broadcast of h for step t+1 ----
        if (t < T_SZ - 1) {
            const int sp = t & 3;                     // 4-deep stage ring
            const float hpart = __shfl_xor_sync(0xffffffffu, h, 8);  // u+1's h
            if (storer)
                stage[sp][ks][slot][j4 >> 1] = pk2(h, hpart);
            __syncthreads();
            if (tid == 0) {
                asm volatile("cp.async.bulk.wait_group.read 2;" ::: "memory");
                asm volatile("fence.proxy.async.shared::cta;" ::: "memory");
                const u32 src = st_l + (u32)sp * 512u;
                const u32 po  = (u32)((b ^ 1) << 12);   // hbuf parity stride 4096B
                const u32 mo  = (u32)((b ^ 1) << 3);
#pragma unroll
                for (int rk = 0; rk < 8; rk++)
                    bulk_s2s(dstc[rk] + po, src, 512u, mrem[rk] + mo);
                asm volatile("cp.async.bulk.commit_group;" ::: "memory");
            }
        }
    }

    // finals: h_T then c_T, each [B, H], appended after Hs
    if (ks < 4) {
        float* fin = out + (size_t)B_SZ * T_SZ * H_SZ;
        fin[(size_t)rowg * H_SZ + u] = h;
        fin[(size_t)B_SZ * H_SZ + (size_t)rowg * H_SZ + u] = c;
    }
}

extern "C" void kernel_launch(void* const* d_in, const int* in_sizes, int n_in,
                              void* d_out, int out_size) {
    const float* x    = (const float*)d_in[0];
    const float* W_i  = (const float*)d_in[1];
    const float* W_h  = (const float*)d_in[2];
    const float* bias = (const float*)d_in[3];
    float* out = (float*)d_out;

    dim3 g1(1024 / 128, (B_SZ * T_SZ) / 128);
    xw_gemm<<<g1, 256>>>(x, W_i, bias);

    repack<<<B_SZ * T_SZ, 256>>>();

    dim3 g2(8, 16);
    lstm_scan<<<g2, 256>>>(W_h, out);
}

// round 12
// speedup vs baseline: 1.0571x; 1.0571x over previous
#include <cuda_runtime.h>
#include <cstdint>
#include <cstddef>

typedef unsigned long long u64;
typedef unsigned int u32;

#define B_SZ 64
#define T_SZ 2048
#define H_SZ 256
#define G4   1024   // 4*H

// scratch: natural layout [m][gate*256+u] (gemm output)
__device__ float g_xg[(size_t)B_SZ * T_SZ * G4];
// scratch: gate-interleaved layout [m][u*4+gate] (scan input)
__device__ float g_xgi[(size_t)B_SZ * T_SZ * G4];

// ---------------- f32x2 helpers ----------------
__device__ __forceinline__ u64 pk2(float lo, float hi) {
    u64 r; asm("mov.b64 %0, {%1, %2};" : "=l"(r) : "f"(lo), "f"(hi)); return r;
}
__device__ __forceinline__ u64 dup2(float a) {
    u64 r; asm("mov.b64 %0, {%1, %1};" : "=l"(r) : "f"(a)); return r;
}
__device__ __forceinline__ u64 fma2(u64 a, u64 b, u64 c) {
    u64 d; asm("fma.rn.f32x2 %0, %1, %2, %3;" : "=l"(d) : "l"(a), "l"(b), "l"(c)); return d;
}
__device__ __forceinline__ u64 add2(u64 a, u64 b) {
    u64 d; asm("add.rn.f32x2 %0, %1, %2;" : "=l"(d) : "l"(a), "l"(b)); return d;
}
__device__ __forceinline__ void unpk(u64 v, float& lo, float& hi) {
    asm("mov.b64 {%0, %1}, %2;" : "=f"(lo), "=f"(hi) : "l"(v));
}

// ---------------- cluster / mbarrier helpers ----------------
__device__ __forceinline__ u32 smem_u32(const void* p) {
    u32 a;
    asm("{ .reg .u64 t; cvta.to.shared.u64 t, %1; cvt.u32.u64 %0, t; }" : "=r"(a) : "l"(p));
    return a;
}
__device__ __forceinline__ u32 mapa_sh(u32 a, u32 rk) {
    u32 r; asm("mapa.shared::cluster.u32 %0, %1, %2;" : "=r"(r) : "r"(a), "r"(rk)); return r;
}
__device__ __forceinline__ void cluster_sync_() {
    asm volatile("barrier.cluster.arrive.aligned;" ::: "memory");
    asm volatile("barrier.cluster.wait.aligned;" ::: "memory");
}
__device__ __forceinline__ void mbar_init(u32 a, u32 cnt) {
    asm volatile("mbarrier.init.shared.b64 [%0], %1;" :: "r"(a), "r"(cnt) : "memory");
}
__device__ __forceinline__ void mbar_expect(u32 a, u32 bytes) {
    asm volatile("mbarrier.arrive.expect_tx.shared.b64 _, [%0], %1;" :: "r"(a), "r"(bytes) : "memory");
}
__device__ __forceinline__ void mbar_wait(u32 a, u32 ph) {
    asm volatile(
        "{\n\t.reg .pred P;\n\t"
        "MW%=:\n\t"
        "mbarrier.try_wait.parity.acquire.cta.shared::cta.b64 P, [%0], %1, 0x989680;\n\t"
        "@!P bra MW%=;\n\t}"
        :: "r"(a), "r"(ph) : "memory");
}
__device__ __forceinline__ void st_async_f32(u32 dst, float v, u32 mb) {
    asm volatile(
        "st.async.shared::cluster.mbarrier::complete_tx::bytes.b32 [%0], %1, [%2];"
        :: "r"(dst), "r"(__float_as_uint(v)), "r"(mb) : "memory");
}

// ---------------- activations (exact, MUFU-based) ----------------
__device__ __forceinline__ float sigm(float x) {
    return __fdividef(1.0f, 1.0f + __expf(-x));
}
__device__ __forceinline__ float tanh_(float x) {
    return 1.0f - __fdividef(2.0f, __expf(2.0f * x) + 1.0f);
}

// =====================================================================
// Phase 1: g_xg[m][1024] = x[m][256] @ W_i[256][1024] + bias
// (unchanged, proven 1.35ms)
// =====================================================================
__global__ __launch_bounds__(256, 2) void xw_gemm(
    const float* __restrict__ A,
    const float* __restrict__ W,
    const float* __restrict__ bias)
{
    __shared__ float As[2][16][132];
    __shared__ float Bs[2][16][132];

    const int tid = threadIdx.x;
    const int tx = tid & 15;
    const int ty = tid >> 4;
    const int mBase = blockIdx.y * 128;
    const int nBase = blockIdx.x * 128;

    const int arow0 = tid >> 2,         akq0 = tid & 3;
    const int arow1 = (tid + 256) >> 2, akq1 = (tid + 256) & 3;
    const int bk0   = tid >> 5,         bnq0 = tid & 31;
    const int bk1   = (tid + 256) >> 5, bnq1 = (tid + 256) & 31;

    u64 acc[8][4];
    {
        const float* bp = bias + nBase + tx * 8;
        u64 b0 = pk2(bp[0], bp[1]);
        u64 b1 = pk2(bp[2], bp[3]);
        u64 b2 = pk2(bp[4], bp[5]);
        u64 b3 = pk2(bp[6], bp[7]);
#pragma unroll
        for (int i = 0; i < 8; i++) { acc[i][0] = b0; acc[i][1] = b1; acc[i][2] = b2; acc[i][3] = b3; }
    }

    float4 a_r0, a_r1, b_r0, b_r1;
    a_r0 = *(const float4*)(A + (size_t)(mBase + arow0) * 256 + akq0 * 4);
    a_r1 = *(const float4*)(A + (size_t)(mBase + arow1) * 256 + akq1 * 4);
    b_r0 = *(const float4*)(W + (size_t)bk0 * 1024 + nBase + bnq0 * 4);
    b_r1 = *(const float4*)(W + (size_t)bk1 * 1024 + nBase + bnq1 * 4);
    As[0][akq0 * 4 + 0][arow0] = a_r0.x; As[0][akq0 * 4 + 1][arow0] = a_r0.y;
    As[0][akq0 * 4 + 2][arow0] = a_r0.z; As[0][akq0 * 4 + 3][arow0] = a_r0.w;
    As[0][akq1 * 4 + 0][arow1] = a_r1.x; As[0][akq1 * 4 + 1][arow1] = a_r1.y;
    As[0][akq1 * 4 + 2][arow1] = a_r1.z; As[0][akq1 * 4 + 3][arow1] = a_r1.w;
    *(float4*)&Bs[0][bk0][bnq0 * 4] = b_r0;
    *(float4*)&Bs[0][bk1][bnq1 * 4] = b_r1;
    __syncthreads();

    int p = 0;
#pragma unroll 1
    for (int kc = 0; kc < 16; kc++) {
        if (kc < 15) {
            const int kb = (kc + 1) * 16;
            a_r0 = *(const float4*)(A + (size_t)(mBase + arow0) * 256 + kb + akq0 * 4);
            a_r1 = *(const float4*)(A + (size_t)(mBase + arow1) * 256 + kb + akq1 * 4);
            b_r0 = *(const float4*)(W + (size_t)(kb + bk0) * 1024 + nBase + bnq0 * 4);
            b_r1 = *(const float4*)(W + (size_t)(kb + bk1) * 1024 + nBase + bnq1 * 4);
        }
#pragma unroll
        for (int k = 0; k < 16; k++) {
            float4 a0 = *(float4*)&As[p][k][ty * 8];
            float4 a1 = *(float4*)&As[p][k][ty * 8 + 4];
            float4 b0 = *(float4*)&Bs[p][k][tx * 8];
            float4 b1 = *(float4*)&Bs[p][k][tx * 8 + 4];
            u64 bb0 = pk2(b0.x, b0.y), bb1 = pk2(b0.z, b0.w);
            u64 bb2 = pk2(b1.x, b1.y), bb3 = pk2(b1.z, b1.w);
            float aa[8] = {a0.x, a0.y, a0.z, a0.w, a1.x, a1.y, a1.z, a1.w};
#pragma unroll
            for (int i = 0; i < 8; i++) {
                u64 ad = dup2(aa[i]);
                acc[i][0] = fma2(ad, bb0, acc[i][0]);
                acc[i][1] = fma2(ad, bb1, acc[i][1]);
                acc[i][2] = fma2(ad, bb2, acc[i][2]);
                acc[i][3] = fma2(ad, bb3, acc[i][3]);
            }
        }
        if (kc < 15) {
            const int pn = p ^ 1;
            As[pn][akq0 * 4 + 0][arow0] = a_r0.x; As[pn][akq0 * 4 + 1][arow0] = a_r0.y;
            As[pn][akq0 * 4 + 2][arow0] = a_r0.z; As[pn][akq0 * 4 + 3][arow0] = a_r0.w;
            As[pn][akq1 * 4 + 0][arow1] = a_r1.x; As[pn][akq1 * 4 + 1][arow1] = a_r1.y;
            As[pn][akq1 * 4 + 2][arow1] = a_r1.z; As[pn][akq1 * 4 + 3][arow1] = a_r1.w;
            *(float4*)&Bs[pn][bk0][bnq0 * 4] = b_r0;
            *(float4*)&Bs[pn][bk1][bnq1 * 4] = b_r1;
            __syncthreads();
            p = pn;
        }
    }

#pragma unroll
    for (int i = 0; i < 8; i++) {
        float o[8];
        unpk(acc[i][0], o[0], o[1]); unpk(acc[i][1], o[2], o[3]);
        unpk(acc[i][2], o[4], o[5]); unpk(acc[i][3], o[6], o[7]);
        float* cp = g_xg + (size_t)(mBase + ty * 8 + i) * 1024 + nBase + tx * 8;
        *(float4*)(cp)     = make_float4(o[0], o[1], o[2], o[3]);
        *(float4*)(cp + 4) = make_float4(o[4], o[5], o[6], o[7]);
    }
}

// =====================================================================
// Repack: [m][gate*256+u] -> [m][u*4+gate]. (unchanged)
// =====================================================================
__global__ __launch_bounds__(256, 8) void repack()
{
    const size_t m = blockIdx.x;
    const int u = threadIdx.x;
    const float* src = g_xg + m * 1024;
    float4 v;
    v.x = src[u];
    v.y = src[256 + u];
    v.z = src[512 + u];
    v.w = src[768 + u];
    *(float4*)(g_xgi + m * 1024 + (size_t)u * 4) = v;
}

// =====================================================================
// Phase 2: recurrent scan (R10 comm structure + critical-path surgery).
// Changes vs R10:
//  - broadcast st.asyncs issued BEFORE the out STG (chain-first)
//  - tid0's mbar_expect re-arm moved AFTER the FMA loop (off wakeup tail)
//  - out STG done by duplicate lanes ks in [4,8) (butterfly round 3 gives
//    lanes ks and ks^4 identical sums; lane r+4 gets h via one shfl and
//    owns the fire-and-forget store; lane r keeps act + broadcast + state)
// =====================================================================
__global__ __launch_bounds__(256, 1) __cluster_dims__(8, 1, 1)
void lstm_scan(const float* __restrict__ Wh, float* __restrict__ out)
{
    __shared__ u64 hbuf[2][4][128];   // [parity][row][k-pair slot]
    __shared__ u64 mbar[2];

    const int tid  = threadIdx.x;
    const int w    = tid >> 5;
    const int lane = tid & 31;
    const int j4   = lane >> 3;          // unit-within-group
    const int ks   = lane & 7;           // k-slice / row id
    const int rank = blockIdx.x;
    const int grp  = blockIdx.y;
    const int u    = rank * 32 + w * 4 + j4;

    // --- weights packed along k: wp[g][m], k-pair kp = ks*16+m ---
    u64 wp[4][16];
#pragma unroll
    for (int m = 0; m < 16; m++) {
        const int kA = ks * 32 + 2 * m;
#pragma unroll
        for (int g = 0; g < 4; g++) {
            wp[g][m] = pk2(Wh[(size_t)kA * 1024 + g * 256 + u],
                           Wh[(size_t)(kA + 1) * 1024 + g * 256 + u]);
        }
    }

    // init: zero parity-0 buffer, init + arm both mbarriers
    {
        u64* hz = &hbuf[0][0][0];
        hz[tid] = 0ull; hz[tid + 256] = 0ull;
    }
    const u32 hb_l = smem_u32(&hbuf[0][0][0]);
    const u32 mb_l = smem_u32(&mbar[0]);
    if (tid == 0) {
        mbar_init(mb_l, 1);
        mbar_init(mb_l + 8, 1);
        mbar_expect(mb_l, 4096);       // buffer 0: fed at t=1, used t=2
        mbar_expect(mb_l + 8, 4096);   // buffer 1: fed at t=0, used t=1
    }
    __syncthreads();
    cluster_sync_();   // peers armed + hbuf[0] zeroed everywhere

    // lane-role constants: rr = ks&3 is the batch row this lane reduces for
    const int rr   = ks & 3;
    const int rowg = grp * 4 + rr;
    const size_t xgBase  = ((size_t)rowg * T_SZ) * 1024 + (size_t)u * 4;
    const size_t outBase = ((size_t)rowg * T_SZ) * H_SZ + u;

    // producer slot for (row=rr, unit u) — only act lanes (ks<4) use it
    const int kp  = u >> 1;
    const int mq  = kp & 15;
    const u32 off0 = (u32)((ks & 3) * 1024 + ((mq >> 1) * 16 + (kp >> 4) * 2 + (mq & 1)) * 8 + (u & 1) * 4);

    u32 hdst[8], mrem[8];
#pragma unroll
    for (int rk = 0; rk < 8; rk++) {
        hdst[rk] = mapa_sh(hb_l, (u32)rk) + off0;
        mrem[rk] = mapa_sh(mb_l, (u32)rk);
    }

    float c = 0.0f, h = 0.0f;
    u32 ph0 = 0, ph1 = 0;

#pragma unroll 1
    for (int t = 0; t < T_SZ; t++) {
        const int b = t & 1;

        // xg prefetch for this step — only act lanes need it
        float4 xq = make_float4(0.f, 0.f, 0.f, 0.f);
        if (ks < 4)
            xq = *(const float4*)(g_xgi + xgBase + (size_t)t * 1024);

        if (t > 0) {
            const u32 phb = b ? ph1 : ph0;
            mbar_wait(mb_l + (b << 3), phb);
            if (b) ph1 ^= 1; else ph0 ^= 1;
        }

        // ---- partial GEMM over this thread's 32-k slice ----
        u64 acc[4][4];
#pragma unroll
        for (int r = 0; r < 4; r++)
#pragma unroll
            for (int g = 0; g < 4; g++) acc[r][g] = 0ull;

        const u64* hbp = &hbuf[b][0][0];
#pragma unroll
        for (int m2 = 0; m2 < 8; m2++) {
#pragma unroll
            for (int r = 0; r < 4; r++) {
                ulonglong2 hv = *(const ulonglong2*)(hbp + r * 128 + m2 * 16 + ks * 2);
#pragma unroll
                for (int g = 0; g < 4; g++) {
                    acc[r][g] = fma2(hv.x, wp[g][2 * m2],     acc[r][g]);
                    acc[r][g] = fma2(hv.y, wp[g][2 * m2 + 1], acc[r][g]);
                }
            }
        }

        // re-arm buffer b for step t+2 (safe: peers' t+1 sends depend on our
        // h(t), which we only send after this point)
        if (t > 0 && tid == 0)
            mbar_expect(mb_l + (b << 3), 4096);

        // ---- warp reduce-scatter over ks ----
        // (round 3 is a butterfly: lanes ks and ks^4 both end with row ks&3)
        const bool pb = (ks & 1);
        const bool qb = (ks & 2);
        u64 kk[4];
#pragma unroll
        for (int g = 0; g < 4; g++) {
            u64 sA = pb ? acc[0][g] : acc[1][g];
            u64 sB = pb ? acc[2][g] : acc[3][g];
            u64 rA = __shfl_xor_sync(0xffffffffu, sA, 1);
            u64 rB = __shfl_xor_sync(0xffffffffu, sB, 1);
            u64 k0 = add2(pb ? acc[1][g] : acc[0][g], rA);
            u64 k1 = add2(pb ? acc[3][g] : acc[2][g], rB);
            u64 s2 = qb ? k0 : k1;
            u64 r2 = __shfl_xor_sync(0xffffffffu, s2, 2);
            u64 kx = add2(qb ? k1 : k0, r2);
            kk[g] = add2(kx, __shfl_xor_sync(0xffffffffu, kx, 4));
        }

        // ---- act lanes (ks<4): activations + broadcast (chain-first) ----
        if (ks < 4) {
            float e0, e1;
            unpk(kk[0], e0, e1); const float gi = e0 + e1 + xq.x;
            unpk(kk[1], e0, e1); const float gf = e0 + e1 + xq.y;
            unpk(kk[2], e0, e1); const float gg = e0 + e1 + xq.z;
            unpk(kk[3], e0, e1); const float go = e0 + e1 + xq.w;

            c = sigm(gf) * c + sigm(gi) * tanh_(gg);
            h = sigm(go) * tanh_(c);

            if (t < T_SZ - 1) {
                const u32 po = (u32)((b ^ 1) << 12);    // parity stride 4096B
                const u32 mo = (u32)((b ^ 1) << 3);
#pragma unroll
                for (int rk = 0; rk < 8; rk++)
                    st_async_f32(hdst[rk] + po, h, mrem[rk] + mo);
            }
        }

        // ---- duplicate lanes (ks>=4): fire-and-forget output store ----
        {
            const float hs = __shfl_xor_sync(0xffffffffu, h, 4);  // h from lane ks^4
            if (ks >= 4)
                out[outBase + (size_t)t * H_SZ] = hs;
        }
    }

    // finals: h_T then c_T, each [B, H], appended after Hs (act lanes hold state)
    if (ks < 4) {
        float* fin = out + (size_t)B_SZ * T_SZ * H_SZ;
        fin[(size_t)rowg * H_SZ + u] = h;
        fin[(size_t)B_SZ * H_SZ + (size_t)rowg * H_SZ + u] = c;
    }
}

extern "C" void kernel_launch(void* const* d_in, const int* in_sizes, int n_in,
                              void* d_out, int out_size) {
    const float* x    = (const float*)d_in[0];
    const float* W_i  = (const float*)d_in[1];
    const float* W_h  = (const float*)d_in[2];
    const float* bias = (const float*)d_in[3];
    float* out = (float*)d_out;

    dim3 g1(1024 / 128, (B_SZ * T_SZ) / 128);
    xw_gemm<<<g1, 256>>>(x, W_i, bias);

    repack<<<B_SZ * T_SZ, 256>>>();

    dim3 g2(8, 16);
    lstm_scan<<<g2, 256>>>(W_h, out);
}

// round 13
// speedup vs baseline: 1.1209x; 1.0604x over previous
#include <cuda_runtime.h>
#include <cstdint>
#include <cstddef>

typedef unsigned long long u64;
typedef unsigned int u32;

#define B_SZ 64
#define T_SZ 2048
#define H_SZ 256
#define G4   1024   // 4*H

// scratch: natural layout [m][gate*256+u] (gemm output)
__device__ float g_xg[(size_t)B_SZ * T_SZ * G4];
// scratch: gate-interleaved layout [m][u*4+gate] (scan input)
__device__ float g_xgi[(size_t)B_SZ * T_SZ * G4];

// ---------------- f32x2 helpers ----------------
__device__ __forceinline__ u64 pk2(float lo, float hi) {
    u64 r; asm("mov.b64 %0, {%1, %2};" : "=l"(r) : "f"(lo), "f"(hi)); return r;
}
__device__ __forceinline__ u64 dup2(float a) {
    u64 r; asm("mov.b64 %0, {%1, %1};" : "=l"(r) : "f"(a)); return r;
}
__device__ __forceinline__ u64 fma2(u64 a, u64 b, u64 c) {
    u64 d; asm("fma.rn.f32x2 %0, %1, %2, %3;" : "=l"(d) : "l"(a), "l"(b), "l"(c)); return d;
}
__device__ __forceinline__ u64 add2(u64 a, u64 b) {
    u64 d; asm("add.rn.f32x2 %0, %1, %2;" : "=l"(d) : "l"(a), "l"(b)); return d;
}
__device__ __forceinline__ void unpk(u64 v, float& lo, float& hi) {
    asm("mov.b64 {%0, %1}, %2;" : "=f"(lo), "=f"(hi) : "l"(v));
}

// ---------------- cluster / mbarrier helpers ----------------
__device__ __forceinline__ u32 smem_u32(const void* p) {
    u32 a;
    asm("{ .reg .u64 t; cvta.to.shared.u64 t, %1; cvt.u32.u64 %0, t; }" : "=r"(a) : "l"(p));
    return a;
}
__device__ __forceinline__ u32 mapa_sh(u32 a, u32 rk) {
    u32 r; asm("mapa.shared::cluster.u32 %0, %1, %2;" : "=r"(r) : "r"(a), "r"(rk)); return r;
}
__device__ __forceinline__ void cluster_sync_() {
    asm volatile("barrier.cluster.arrive.aligned;" ::: "memory");
    asm volatile("barrier.cluster.wait.aligned;" ::: "memory");
}
__device__ __forceinline__ void mbar_init(u32 a, u32 cnt) {
    asm volatile("mbarrier.init.shared.b64 [%0], %1;" :: "r"(a), "r"(cnt) : "memory");
}
__device__ __forceinline__ void mbar_expect(u32 a, u32 bytes) {
    asm volatile("mbarrier.arrive.expect_tx.shared.b64 _, [%0], %1;" :: "r"(a), "r"(bytes) : "memory");
}
__device__ __forceinline__ void mbar_wait(u32 a, u32 ph) {
    asm volatile(
        "{\n\t.reg .pred P;\n\t"
        "MW%=:\n\t"
        "mbarrier.try_wait.parity.acquire.cta.shared::cta.b64 P, [%0], %1, 0x989680;\n\t"
        "@!P bra MW%=;\n\t}"
        :: "r"(a), "r"(ph) : "memory");
}
__device__ __forceinline__ void st_async_f32(u32 dst, float v, u32 mb) {
    asm volatile(
        "st.async.shared::cluster.mbarrier::complete_tx::bytes.b32 [%0], %1, [%2];"
        :: "r"(dst), "r"(__float_as_uint(v)), "r"(mb) : "memory");
}

// ---------------- activations (exact, MUFU-based) ----------------
__device__ __forceinline__ float sigm(float x) {
    return __fdividef(1.0f, 1.0f + __expf(-x));
}
__device__ __forceinline__ float tanh_(float x) {
    return 1.0f - __fdividef(2.0f, __expf(2.0f * x) + 1.0f);
}

// =====================================================================
// Phase 1: g_xg[m][1024] = x[m][256] @ W_i[256][1024] + bias
// (unchanged, proven 1.35ms)
// =====================================================================
__global__ __launch_bounds__(256, 2) void xw_gemm(
    const float* __restrict__ A,
    const float* __restrict__ W,
    const float* __restrict__ bias)
{
    __shared__ float As[2][16][132];
    __shared__ float Bs[2][16][132];

    const int tid = threadIdx.x;
    const int tx = tid & 15;
    const int ty = tid >> 4;
    const int mBase = blockIdx.y * 128;
    const int nBase = blockIdx.x * 128;

    const int arow0 = tid >> 2,         akq0 = tid & 3;
    const int arow1 = (tid + 256) >> 2, akq1 = (tid + 256) & 3;
    const int bk0   = tid >> 5,         bnq0 = tid & 31;
    const int bk1   = (tid + 256) >> 5, bnq1 = (tid + 256) & 31;

    u64 acc[8][4];
    {
        const float* bp = bias + nBase + tx * 8;
        u64 b0 = pk2(bp[0], bp[1]);
        u64 b1 = pk2(bp[2], bp[3]);
        u64 b2 = pk2(bp[4], bp[5]);
        u64 b3 = pk2(bp[6], bp[7]);
#pragma unroll
        for (int i = 0; i < 8; i++) { acc[i][0] = b0; acc[i][1] = b1; acc[i][2] = b2; acc[i][3] = b3; }
    }

    float4 a_r0, a_r1, b_r0, b_r1;
    a_r0 = *(const float4*)(A + (size_t)(mBase + arow0) * 256 + akq0 * 4);
    a_r1 = *(const float4*)(A + (size_t)(mBase + arow1) * 256 + akq1 * 4);
    b_r0 = *(const float4*)(W + (size_t)bk0 * 1024 + nBase + bnq0 * 4);
    b_r1 = *(const float4*)(W + (size_t)bk1 * 1024 + nBase + bnq1 * 4);
    As[0][akq0 * 4 + 0][arow0] = a_r0.x; As[0][akq0 * 4 + 1][arow0] = a_r0.y;
    As[0][akq0 * 4 + 2][arow0] = a_r0.z; As[0][akq0 * 4 + 3][arow0] = a_r0.w;
    As[0][akq1 * 4 + 0][arow1] = a_r1.x; As[0][akq1 * 4 + 1][arow1] = a_r1.y;
    As[0][akq1 * 4 + 2][arow1] = a_r1.z; As[0][akq1 * 4 + 3][arow1] = a_r1.w;
    *(float4*)&Bs[0][bk0][bnq0 * 4] = b_r0;
    *(float4*)&Bs[0][bk1][bnq1 * 4] = b_r1;
    __syncthreads();

    int p = 0;
#pragma unroll 1
    for (int kc = 0; kc < 16; kc++) {
        if (kc < 15) {
            const int kb = (kc + 1) * 16;
            a_r0 = *(const float4*)(A + (size_t)(mBase + arow0) * 256 + kb + akq0 * 4);
            a_r1 = *(const float4*)(A + (size_t)(mBase + arow1) * 256 + kb + akq1 * 4);
            b_r0 = *(const float4*)(W + (size_t)(kb + bk0) * 1024 + nBase + bnq0 * 4);
            b_r1 = *(const float4*)(W + (size_t)(kb + bk1) * 1024 + nBase + bnq1 * 4);
        }
#pragma unroll
        for (int k = 0; k < 16; k++) {
            float4 a0 = *(float4*)&As[p][k][ty * 8];
            float4 a1 = *(float4*)&As[p][k][ty * 8 + 4];
            float4 b0 = *(float4*)&Bs[p][k][tx * 8];
            float4 b1 = *(float4*)&Bs[p][k][tx * 8 + 4];
            u64 bb0 = pk2(b0.x, b0.y), bb1 = pk2(b0.z, b0.w);
            u64 bb2 = pk2(b1.x, b1.y), bb3 = pk2(b1.z, b1.w);
            float aa[8] = {a0.x, a0.y, a0.z, a0.w, a1.x, a1.y, a1.z, a1.w};
#pragma unroll
            for (int i = 0; i < 8; i++) {
                u64 ad = dup2(aa[i]);
                acc[i][0] = fma2(ad, bb0, acc[i][0]);
                acc[i][1] = fma2(ad, bb1, acc[i][1]);
                acc[i][2] = fma2(ad, bb2, acc[i][2]);
                acc[i][3] = fma2(ad, bb3, acc[i][3]);
            }
        }
        if (kc < 15) {
            const int pn = p ^ 1;
            As[pn][akq0 * 4 + 0][arow0] = a_r0.x; As[pn][akq0 * 4 + 1][arow0] = a_r0.y;
            As[pn][akq0 * 4 + 2][arow0] = a_r0.z; As[pn][akq0 * 4 + 3][arow0] = a_r0.w;
            As[pn][akq1 * 4 + 0][arow1] = a_r1.x; As[pn][akq1 * 4 + 1][arow1] = a_r1.y;
            As[pn][akq1 * 4 + 2][arow1] = a_r1.z; As[pn][akq1 * 4 + 3][arow1] = a_r1.w;
            *(float4*)&Bs[pn][bk0][bnq0 * 4] = b_r0;
            *(float4*)&Bs[pn][bk1][bnq1 * 4] = b_r1;
            __syncthreads();
            p = pn;
        }
    }

#pragma unroll
    for (int i = 0; i < 8; i++) {
        float o[8];
        unpk(acc[i][0], o[0], o[1]); unpk(acc[i][1], o[2], o[3]);
        unpk(acc[i][2], o[4], o[5]); unpk(acc[i][3], o[6], o[7]);
        float* cp = g_xg + (size_t)(mBase + ty * 8 + i) * 1024 + nBase + tx * 8;
        *(float4*)(cp)     = make_float4(o[0], o[1], o[2], o[3]);
        *(float4*)(cp + 4) = make_float4(o[4], o[5], o[6], o[7]);
    }
}

// =====================================================================
// Repack: [m][gate*256+u] -> [m][u*4+gate]. (unchanged)
// =====================================================================
__global__ __launch_bounds__(256, 8) void repack()
{
    const size_t m = blockIdx.x;
    const int u = threadIdx.x;
    const float* src = g_xg + m * 1024;
    float4 v;
    v.x = src[u];
    v.y = src[256 + u];
    v.z = src[512 + u];
    v.w = src[768 + u];
    *(float4*)(g_xgi + m * 1024 + (size_t)u * 4) = v;
}

// =====================================================================
// Phase 2: recurrent scan, two interleaved batch-groups per cluster.
// Grid (8,8), cluster (8,1,1). Cluster cg owns batch rows 8*cg..8*cg+7:
// group 0 = rows +0..3, group 1 = rows +4..7. Per step t, the CTA runs
// segment(g=0) then segment(g=1); while one group's h is in DSMEM
// flight, the other group's FMA/reduce/act fills the gap.
// Weights (wp) are shared across rows -> register cost unchanged.
// hbuf[group][parity][row][slot], 4 mbarriers (group x parity).
// Keeps R12's surgery: chain-first send, deferred re-arm, STG offload
// to duplicate lanes.
// =====================================================================
__global__ __launch_bounds__(256, 1) __cluster_dims__(8, 1, 1)
void lstm_scan(const float* __restrict__ Wh, float* __restrict__ out)
{
    __shared__ u64 hbuf[2][2][4][128];   // 16KB: [group][parity][row][slot]
    __shared__ u64 mbar[4];              // [group*2 + parity]

    const int tid  = threadIdx.x;
    const int w    = tid >> 5;
    const int lane = tid & 31;
    const int j4   = lane >> 3;          // unit-within-group
    const int ks   = lane & 7;           // k-slice / row id
    const int rank = blockIdx.x;
    const int cg   = blockIdx.y;         // cluster group 0..7
    const int u    = rank * 32 + w * 4 + j4;

    // --- weights packed along k: wp[g][m], k-pair kp = ks*16+m ---
    u64 wp[4][16];
#pragma unroll
    for (int m = 0; m < 16; m++) {
        const int kA = ks * 32 + 2 * m;
#pragma unroll
        for (int g = 0; g < 4; g++) {
            wp[g][m] = pk2(Wh[(size_t)kA * 1024 + g * 256 + u],
                           Wh[(size_t)(kA + 1) * 1024 + g * 256 + u]);
        }
    }

    // init: zero parity-0 buffers of both groups, arm all 4 mbarriers
    {
        u64* h0 = &hbuf[0][0][0][0];
        u64* h1 = &hbuf[1][0][0][0];
        h0[tid] = 0ull; h0[tid + 256] = 0ull;
        h1[tid] = 0ull; h1[tid + 256] = 0ull;
    }
    const u32 hb_l = smem_u32(&hbuf[0][0][0][0]);
    const u32 mb_l = smem_u32(&mbar[0]);
    if (tid == 0) {
#pragma unroll
        for (int i = 0; i < 4; i++) {
            mbar_init(mb_l + i * 8, 1);
            mbar_expect(mb_l + i * 8, 4096);
        }
    }
    __syncthreads();
    cluster_sync_();   // peers armed + parity-0 buffers zeroed everywhere

    // lane-role constants: rr = ks&3 is the batch row-within-group
    const int rr = ks & 3;
    // group 0 / group 1 global rows
    const int row0 = cg * 8 + rr;
    const int row1 = cg * 8 + 4 + rr;
    const size_t xgBase0  = ((size_t)row0 * T_SZ) * 1024 + (size_t)u * 4;
    const size_t xgBase1  = ((size_t)row1 * T_SZ) * 1024 + (size_t)u * 4;
    const size_t outBase0 = ((size_t)row0 * T_SZ) * H_SZ + u;
    const size_t outBase1 = ((size_t)row1 * T_SZ) * H_SZ + u;

    // producer slot for (row=rr, unit u) within a [4][128] buffer
    const int kp  = u >> 1;
    const int mq  = kp & 15;
    const u32 off0 = (u32)(rr * 1024 + ((mq >> 1) * 16 + (kp >> 4) * 2 + (mq & 1)) * 8 + (u & 1) * 4);

    u32 hdst[8], mrem[8];
#pragma unroll
    for (int rk = 0; rk < 8; rk++) {
        hdst[rk] = mapa_sh(hb_l, (u32)rk) + off0;   // + group*8192 + parity*4096
        mrem[rk] = mapa_sh(mb_l, (u32)rk);          // + (group*2+parity)*8
    }

    float c0 = 0.0f, h0 = 0.0f, c1 = 0.0f, h1 = 0.0f;
    u32 ph[4] = {0, 0, 0, 0};   // phase per (group*2 + parity)

#pragma unroll 1
    for (int t = 0; t < T_SZ; t++) {
        const int b = t & 1;

#pragma unroll
        for (int g = 0; g < 2; g++) {
            const u32 gboff = (u32)(g * 8192 + b * 4096);   // hbuf byte offset
            const u32 moff  = (u32)((g * 2 + b) * 8);       // mbar byte offset

            // xg prefetch for this segment — act lanes only
            float4 xq = make_float4(0.f, 0.f, 0.f, 0.f);
            if (ks < 4)
                xq = *(const float4*)(g_xgi + (g ? xgBase1 : xgBase0) + (size_t)t * 1024);

            if (t > 0) {
                mbar_wait(mb_l + moff, ph[g * 2 + b]);
                ph[g * 2 + b] ^= 1;
            }

            // ---- partial GEMM over this thread's 32-k slice ----
            u64 acc[4][4];
#pragma unroll
            for (int r = 0; r < 4; r++)
#pragma unroll
                for (int gg = 0; gg < 4; gg++) acc[r][gg] = 0ull;

            const u64* hbp = &hbuf[g][b][0][0];
#pragma unroll
            for (int m2 = 0; m2 < 8; m2++) {
#pragma unroll
                for (int r = 0; r < 4; r++) {
                    ulonglong2 hv = *(const ulonglong2*)(hbp + r * 128 + m2 * 16 + ks * 2);
#pragma unroll
                    for (int gg = 0; gg < 4; gg++) {
                        acc[r][gg] = fma2(hv.x, wp[gg][2 * m2],     acc[r][gg]);
                        acc[r][gg] = fma2(hv.y, wp[gg][2 * m2 + 1], acc[r][gg]);
                    }
                }
            }

            // deferred re-arm of this (group,parity) for step t+2
            if (t > 0 && tid == 0)
                mbar_expect(mb_l + moff, 4096);

            // ---- warp reduce-scatter over ks ----
            const bool pb = (ks & 1);
            const bool qb = (ks & 2);
            u64 kk[4];
#pragma unroll
            for (int gg = 0; gg < 4; gg++) {
                u64 sA = pb ? acc[0][gg] : acc[1][gg];
                u64 sB = pb ? acc[2][gg] : acc[3][gg];
                u64 rA = __shfl_xor_sync(0xffffffffu, sA, 1);
                u64 rB = __shfl_xor_sync(0xffffffffu, sB, 1);
                u64 k0 = add2(pb ? acc[1][gg] : acc[0][gg], rA);
                u64 k1 = add2(pb ? acc[3][gg] : acc[2][gg], rB);
                u64 s2 = qb ? k0 : k1;
                u64 r2 = __shfl_xor_sync(0xffffffffu, s2, 2);
                u64 kx = add2(qb ? k1 : k0, r2);
                kk[gg] = add2(kx, __shfl_xor_sync(0xffffffffu, kx, 4));
            }

            float hcur = 0.0f;
            // ---- act lanes: activations + chain-first broadcast ----
            if (ks < 4) {
                float e0, e1;
                unpk(kk[0], e0, e1); const float gi = e0 + e1 + xq.x;
                unpk(kk[1], e0, e1); const float gf = e0 + e1 + xq.y;
                unpk(kk[2], e0, e1); const float gg_ = e0 + e1 + xq.z;
                unpk(kk[3], e0, e1); const float go = e0 + e1 + xq.w;

                float cv = g ? c1 : c0;
                cv = sigm(gf) * cv + sigm(gi) * tanh_(gg_);
                hcur = sigm(go) * tanh_(cv);
                if (g) { c1 = cv; h1 = hcur; } else { c0 = cv; h0 = hcur; }

                if (t < T_SZ - 1) {
                    const u32 po = (u32)(g * 8192 + (b ^ 1) * 4096);
                    const u32 mo = (u32)((g * 2 + (b ^ 1)) * 8);
#pragma unroll
                    for (int rk = 0; rk < 8; rk++)
                        st_async_f32(hdst[rk] + po, hcur, mrem[rk] + mo);
                }
            }

            // ---- duplicate lanes: fire-and-forget output store ----
            {
                const float hs = __shfl_xor_sync(0xffffffffu, hcur, 4);
                if (ks >= 4)
                    out[(g ? outBase1 : outBase0) + (size_t)t * H_SZ] = hs;
            }
        }
    }

    // finals: h_T then c_T, each [B, H], appended after Hs
    if (ks < 4) {
        float* fin = out + (size_t)B_SZ * T_SZ * H_SZ;
        fin[(size_t)row0 * H_SZ + u] = h0;
        fin[(size_t)B_SZ * H_SZ + (size_t)row0 * H_SZ + u] = c0;
        fin[(size_t)row1 * H_SZ + u] = h1;
        fin[(size_t)B_SZ * H_SZ + (size_t)row1 * H_SZ + u] = c1;
    }
}

extern "C" void kernel_launch(void* const* d_in, const int* in_sizes, int n_in,
                              void* d_out, int out_size) {
    const float* x    = (const float*)d_in[0];
    const float* W_i  = (const float*)d_in[1];
    const float* W_h  = (const float*)d_in[2];
    const float* bias = (const float*)d_in[3];
    float* out = (float*)d_out;

    dim3 g1(1024 / 128, (B_SZ * T_SZ) / 128);
    xw_gemm<<<g1, 256>>>(x, W_i, bias);

    repack<<<B_SZ * T_SZ, 256>>>();

    dim3 g2(8, 8);
    lstm_scan<<<g2, 256>>>(W_h, out);
}